// round 8
// baseline (speedup 1.0000x reference)
#include <cuda_runtime.h>
#include <cuda_fp16.h>
#include <cstdint>
#include <math.h>

#define B_DIM 64
#define S_DIM 2048
#define D_DIM 512

#define BLK_S 128
#define NTHREADS 256
#define NMACRO 32            // 4 ei * 8 kt (k-tile = 64)
#define NSTAGE 3
#define STG_WORDS 8192       // A 4096 words (8192 fp16) + B 4096 words
#define CONST_OFF (NSTAGE * STG_WORDS)          // 24576
#define SMEM_WORDS (CONST_OFF + 1664)           // 104960 B -> 2 CTAs/SM

// scratch (no device mallocs; __device__ globals are the sanctioned path)
__device__ __half   g_ref16[(size_t)B_DIM * S_DIM * D_DIM];   // fp16 copy of ref (per-CTA self-converted)
__device__ uint32_t g_w16[NMACRO * 4096];                     // W fp16, fragment-ordered
__device__ float    g_qpb[B_DIM * D_DIM];                     // q + Wq_b + Wr_b

// ---------------------------------------------------------------------------
// prep: [0,256): W -> fragment-ordered fp16 pairs
//       [256,1280): q projection
// ---------------------------------------------------------------------------
__global__ void prep_kernel(const float* __restrict__ Wr_w,
                            const float* __restrict__ query,
                            const float* __restrict__ Wq_w,
                            const float* __restrict__ Wq_b,
                            const float* __restrict__ Wr_b) {
    if (blockIdx.x < 256) {
        int o = blockIdx.x * 256 + threadIdx.x;
        #pragma unroll
        for (int it = 0; it < 2; it++, o += 65536) {
            const int g = o >> 12, rem = o & 4095;
            const int c = rem >> 2, w = rem & 3;
            const int lane = c & 31, t = c >> 5;
            const int j = t & 3, we = (t >> 2) & 1, ks = t >> 3;
            const int ei = g >> 3, kt = g & 7;
            const int tn = j * 2 + (w >> 1);
            const int e = ei * 128 + we * 64 + tn * 8 + (lane >> 2);
            const int k = kt * 64 + ks * 16 + 2 * (lane & 3) + (w & 1) * 8;
            __half2 h = __floats2half2_rn(Wr_w[e * D_DIM + k], Wr_w[e * D_DIM + k + 1]);
            g_w16[o] = *reinterpret_cast<uint32_t*>(&h);
        }
    } else {
        __shared__ float qs[D_DIM];
        const int id2 = blockIdx.x - 256;
        const int b = id2 & 63;
        const int eblk = id2 >> 6;
        const int tid = threadIdx.x, lane = tid & 31, w = tid >> 5;
        for (int i = tid; i < D_DIM; i += 256) qs[i] = query[(size_t)b * D_DIM + i];
        __syncthreads();
        const int e0 = eblk * 32 + w * 4;
        #pragma unroll
        for (int k = 0; k < 4; k++) {
            const int e = e0 + k;
            const float* wr = Wq_w + (size_t)e * D_DIM;
            float s = 0.f;
            #pragma unroll
            for (int d = lane; d < D_DIM; d += 32) s += qs[d] * wr[d];
            #pragma unroll
            for (int o = 16; o; o >>= 1) s += __shfl_xor_sync(0xffffffffu, s, o);
            if (lane == 0) g_qpb[b * D_DIM + e] = s + Wq_b[e] + Wr_b[e];
        }
    }
}

// ---------------------------------------------------------------------------
// helpers
// ---------------------------------------------------------------------------
__device__ __forceinline__ void cp16(void* dst, const void* src) {
    unsigned s = (unsigned)__cvta_generic_to_shared(dst);
    asm volatile("cp.async.cg.shared.global [%0], [%1], 16;"
                 :: "r"(s), "l"(src) : "memory");
}
__device__ __forceinline__ float tanha(float x) {
    float y;
    asm("tanh.approx.f32 %0, %1;" : "=f"(y) : "f"(x));
    return y;
}
__device__ __forceinline__ void ldm4(unsigned& r0, unsigned& r1, unsigned& r2,
                                     unsigned& r3, unsigned addr) {
    asm volatile("ldmatrix.sync.aligned.m8n8.x4.shared.b16 {%0,%1,%2,%3}, [%4];"
                 : "=r"(r0), "=r"(r1), "=r"(r2), "=r"(r3) : "r"(addr));
}

#define SM_BIAS(i) sm[CONST_OFF + (i)]
#define SM_QPB(i)  sm[CONST_OFF + 512 + (i)]
#define SM_V(i)    sm[CONST_OFF + 1024 + (i)]
#define SM_L(i)    sm[CONST_OFF + 1536 + (i)]

// ---------------------------------------------------------------------------
// main: phase-0 per-CTA fp32->fp16 conversion, then fp16 m16n8k16 HMMA
//       flattened 32-iteration mainloop with 3-stage cp.async ring
// ---------------------------------------------------------------------------
__global__ void __launch_bounds__(NTHREADS, 2)
attn_main(const float* __restrict__ ref,
          const float* __restrict__ Wr_b,
          const float* __restrict__ value,
          float* __restrict__ out_r,
          float* __restrict__ out_logits)
{
    extern __shared__ float sm[];
    const int tid    = threadIdx.x;
    const int lane   = tid & 31;
    const int warp   = tid >> 5;
    const int warp_s = warp & 3;
    const int warp_e = warp >> 2;
    const int b  = blockIdx.y;
    const int s0 = blockIdx.x * BLK_S;

    const __half* aG = g_ref16 + ((size_t)b * S_DIM + s0) * D_DIM;
    float* outr_b = out_r + (size_t)b * D_DIM * S_DIM;

    // ---- phase 0: convert own A tile fp32 -> fp16 ----
    // tile = 128 rows * 512 floats = 16384 float4 -> 64 per thread
    {
        const float4* a32 =
            reinterpret_cast<const float4*>(ref + ((size_t)b * S_DIM + s0) * D_DIM);
        uint2* a16 = reinterpret_cast<uint2*>(
            g_ref16 + ((size_t)b * S_DIM + s0) * D_DIM);
        #pragma unroll 8
        for (int i = 0; i < 64; i++) {
            const int idx = i * 256 + tid;
            const float4 v = a32[idx];
            __half2 h0 = __floats2half2_rn(v.x, v.y);
            __half2 h1 = __floats2half2_rn(v.z, v.w);
            uint2 o;
            o.x = *reinterpret_cast<const uint32_t*>(&h0);
            o.y = *reinterpret_cast<const uint32_t*>(&h1);
            a16[idx] = o;
        }
        __threadfence();   // drain STGs to L2 before cp.async (L2 path) reads them
    }
    __syncthreads();

    // ---- prefetch stages 0 and 1 ----
    #pragma unroll
    for (int gp = 0; gp < 2; gp++) {
        __half* sa = reinterpret_cast<__half*>(sm + gp * STG_WORDS);
        uint32_t* sb = reinterpret_cast<uint32_t*>(sm) + gp * STG_WORDS + 4096;
        const __half* asrc = aG + (gp & 7) * 64;
        const uint32_t* bsrc = g_w16 + (size_t)gp * 4096;
        #pragma unroll
        for (int i = 0; i < 4; i++) {
            const int ca = tid + i * 256;
            const int row = ca >> 3, gc = ca & 7;
            cp16(sa + row * 64 + ((gc ^ (row & 7)) << 3),
                 asrc + (size_t)row * D_DIM + gc * 8);
            cp16(sb + ca * 4, bsrc + ca * 4);
        }
        asm volatile("cp.async.commit_group;" ::: "memory");
    }

    // epilogue constants
    for (int i = tid; i < D_DIM; i += NTHREADS) {
        SM_BIAS(i) = Wr_b[i];
        SM_QPB(i)  = g_qpb[b * D_DIM + i];
        SM_V(i)    = value[i];
    }
    if (tid < BLK_S) SM_L(tid) = 0.0f;

    // ldmatrix per-thread selectors (invariant)
    const int lrow  = (lane & 15);
    const int lgsel = (lane >> 4) & 1;

    float acc[2][8][4];
    #pragma unroll
    for (int tm = 0; tm < 2; tm++)
        #pragma unroll
        for (int tn = 0; tn < 8; tn++)
            #pragma unroll
            for (int i = 0; i < 4; i++) acc[tm][tn][i] = 0.f;

    unsigned af[2][2][4];
    uint4    bq[4];

    #pragma unroll 1
    for (int g = 0; g < NMACRO; g++) {
        if (g == NMACRO - 1)
            asm volatile("cp.async.wait_group 0;" ::: "memory");
        else
            asm volatile("cp.async.wait_group 1;" ::: "memory");
        __syncthreads();

        // prefetch stage g+2
        if (g + 2 < NMACRO) {
            const int gp = g + 2;
            const int slot = gp % NSTAGE;
            __half* sa = reinterpret_cast<__half*>(sm + slot * STG_WORDS);
            uint32_t* sb = reinterpret_cast<uint32_t*>(sm) + slot * STG_WORDS + 4096;
            const __half* asrc = aG + (gp & 7) * 64;
            const uint32_t* bsrc = g_w16 + (size_t)gp * 4096;
            #pragma unroll
            for (int i = 0; i < 4; i++) {
                const int ca = tid + i * 256;
                const int row = ca >> 3, gc = ca & 7;
                cp16(sa + row * 64 + ((gc ^ (row & 7)) << 3),
                     asrc + (size_t)row * D_DIM + gc * 8);
                cp16(sb + ca * 4, bsrc + ca * 4);
            }
            asm volatile("cp.async.commit_group;" ::: "memory");
        }

        const int slot = g % NSTAGE;
        const unsigned saddr =
            (unsigned)__cvta_generic_to_shared(sm + slot * STG_WORDS);
        const uint32_t* sb =
            reinterpret_cast<const uint32_t*>(sm) + slot * STG_WORDS + 4096;

        // ldmatrix slice 0 into buffer 0
        #pragma unroll
        for (int tm = 0; tm < 2; tm++) {
            const int r = warp_s * 32 + tm * 16 + lrow;
            const unsigned a = saddr + ((r * 8 + (lgsel ^ (r & 7))) << 4);
            ldm4(af[0][tm][0], af[0][tm][1], af[0][tm][2], af[0][tm][3], a);
        }

        #pragma unroll
        for (int ks = 0; ks < 4; ks++) {
            const int pb = ks & 1;
            const uint32_t* sbk = sb + ks * 1024 + warp_e * 512 + lane * 4;
            #pragma unroll
            for (int j = 0; j < 4; j++)
                bq[j] = *reinterpret_cast<const uint4*>(sbk + j * 128);
            if (ks < 3) {
                const int nb = pb ^ 1;
                const int gc = (ks + 1) * 2 + lgsel;
                #pragma unroll
                for (int tm = 0; tm < 2; tm++) {
                    const int r = warp_s * 32 + tm * 16 + lrow;
                    const unsigned a = saddr + ((r * 8 + (gc ^ (r & 7))) << 4);
                    ldm4(af[nb][tm][0], af[nb][tm][1], af[nb][tm][2], af[nb][tm][3], a);
                }
            }
            #pragma unroll
            for (int tm = 0; tm < 2; tm++)
                #pragma unroll
                for (int tn = 0; tn < 8; tn++) {
                    const unsigned b0 = (tn & 1) ? bq[tn >> 1].z : bq[tn >> 1].x;
                    const unsigned b1 = (tn & 1) ? bq[tn >> 1].w : bq[tn >> 1].y;
                    asm volatile(
                        "mma.sync.aligned.m16n8k16.row.col.f32.f16.f16.f32 "
                        "{%0,%1,%2,%3}, {%4,%5,%6,%7}, {%8,%9}, {%0,%1,%2,%3};"
                        : "+f"(acc[tm][tn][0]), "+f"(acc[tm][tn][1]),
                          "+f"(acc[tm][tn][2]), "+f"(acc[tm][tn][3])
                        : "r"(af[pb][tm][0]), "r"(af[pb][tm][1]),
                          "r"(af[pb][tm][2]), "r"(af[pb][tm][3]),
                          "r"(b0), "r"(b1));
                }
        }

        // -------- epilogue at each ei boundary --------
        if ((g & 7) == 7) {
            const int ei = g >> 3;
            float lp[2][2] = {{0.f, 0.f}, {0.f, 0.f}};
            const int sg0 = s0 + warp_s * 32 + (lane >> 2);
            #pragma unroll
            for (int tm = 0; tm < 2; tm++) {
                const int srow = sg0 + tm * 16;
                #pragma unroll
                for (int tn = 0; tn < 8; tn++) {
                    const int e = ei * 128 + warp_e * 64 + tn * 8 + 2 * (lane & 3);
                    const float b0 = SM_BIAS(e), b1 = SM_BIAS(e + 1);
                    const float a0 = acc[tm][tn][0], a1 = acc[tm][tn][1];
                    const float a2 = acc[tm][tn][2], a3 = acc[tm][tn][3];
                    outr_b[(size_t)e       * S_DIM + srow]     = a0 + b0;
                    outr_b[(size_t)(e + 1) * S_DIM + srow]     = a1 + b1;
                    outr_b[(size_t)e       * S_DIM + srow + 8] = a2 + b0;
                    outr_b[(size_t)(e + 1) * S_DIM + srow + 8] = a3 + b1;
                    const float q0 = SM_QPB(e), q1 = SM_QPB(e + 1);
                    const float v0 = SM_V(e), v1 = SM_V(e + 1);
                    lp[tm][0] += tanha(q0 + a0) * v0 + tanha(q1 + a1) * v1;
                    lp[tm][1] += tanha(q0 + a2) * v0 + tanha(q1 + a3) * v1;
                    acc[tm][tn][0] = 0.f; acc[tm][tn][1] = 0.f;
                    acc[tm][tn][2] = 0.f; acc[tm][tn][3] = 0.f;
                }
            }
            #pragma unroll
            for (int tm = 0; tm < 2; tm++)
                #pragma unroll
                for (int h = 0; h < 2; h++) {
                    float v = lp[tm][h];
                    v += __shfl_xor_sync(0xffffffffu, v, 1);
                    v += __shfl_xor_sync(0xffffffffu, v, 2);
                    if ((lane & 3) == 0)
                        atomicAdd(&SM_L(warp_s * 32 + tm * 16 + h * 8 + (lane >> 2)), v);
                }
        }
    }

    __syncthreads();
    if (tid < BLK_S)
        out_logits[(size_t)b * S_DIM + s0 + tid] = 10.0f * tanha(SM_L(tid));
}

// ---------------------------------------------------------------------------
// launch
// ---------------------------------------------------------------------------
extern "C" void kernel_launch(void* const* d_in, const int* in_sizes, int n_in,
                              void* d_out, int out_size) {
    const float* query = (const float*)d_in[0];
    const float* ref   = (const float*)d_in[1];
    const float* Wq_w  = (const float*)d_in[2];
    const float* Wq_b  = (const float*)d_in[3];
    const float* Wr_w  = (const float*)d_in[4];
    const float* Wr_b  = (const float*)d_in[5];
    const float* value = (const float*)d_in[6];
    (void)in_sizes; (void)n_in; (void)out_size;

    float* out        = (float*)d_out;
    float* out_r      = out;                                   // [B, D, S]
    float* out_logits = out + (size_t)B_DIM * D_DIM * S_DIM;   // [B, S]

    prep_kernel<<<1280, 256>>>(Wr_w, query, Wq_w, Wq_b, Wr_b);

    const size_t smem = SMEM_WORDS * sizeof(float);
    cudaFuncSetAttribute(attn_main, cudaFuncAttributeMaxDynamicSharedMemorySize,
                         (int)smem);
    dim3 grid(S_DIM / BLK_S, B_DIM);
    attn_main<<<grid, NTHREADS, smem>>>(ref, Wr_b, value, out_r, out_logits);
}